// round 4
// baseline (speedup 1.0000x reference)
#include <cuda_runtime.h>
#include <math.h>

// ---------------------------------------------------------------------------
// SwinTransformerBlock  B=16, C=384, H=W=64, WS=8, SHIFT=4, HEADS=8, hd=48
// 65536 tokens. All fp32.
// ---------------------------------------------------------------------------

static constexpr int TOKS = 65536;   // B*H*W

// Scratch (zero-init .bss style device globals; no runtime allocation)
__device__ float g_ln1[25165824];    // 65536*384   LN1 output, window-ordered
__device__ float g_qkv[75497472];    // 65536*1152  QKV output, window-ordered
__device__ float g_att[25165824];    // 65536*384   attn output, NATURAL order
__device__ float g_xc [25165824];    // 65536*384   proj output (xc), natural
__device__ float g_ln2[25165824];    // 65536*384   LN2 output
__device__ float g_hid[100663296];   // 65536*1536  MLP hidden
__device__ float g_t  [25165824];    // 65536*384   MLP output (t)

template<int ID> __device__ __forceinline__ float* gbuf();
template<> __device__ __forceinline__ float* gbuf<0>() { return g_ln1; }
template<> __device__ __forceinline__ float* gbuf<1>() { return g_qkv; }
template<> __device__ __forceinline__ float* gbuf<2>() { return g_att; }
template<> __device__ __forceinline__ float* gbuf<3>() { return g_xc;  }
template<> __device__ __forceinline__ float* gbuf<4>() { return g_ln2; }
template<> __device__ __forceinline__ float* gbuf<5>() { return g_hid; }
template<> __device__ __forceinline__ float* gbuf<6>() { return g_t;   }

// ---------------------------------------------------------------------------
// Kernel 1: shift + window partition + LayerNorm1.
// One block per (b, h) image row (1024 blocks). Input x is (B,C,H,W).
// Output row index = window-ordered token id: win*64 + n  where the token's
// shifted coords are hh' = (h-4)&63, ww' = (w-4)&63.
// ---------------------------------------------------------------------------
__global__ void __launch_bounds__(256) ln1_kernel(const float* __restrict__ x,
                                                  const float* __restrict__ gamma,
                                                  const float* __restrict__ beta) {
    const int bh = blockIdx.x;
    const int b = bh >> 6, h = bh & 63;
    const int t = threadIdx.x;                 // 256
    const int tok = t & 63, grp = t >> 6;      // 64 tokens x 4 channel groups
    const float* base = x + (size_t)b * 384 * 4096 + h * 64;

    // pass 1: per-token sum / sumsq (coalesced: fixed c, 64 consecutive w)
    float s = 0.f, q = 0.f;
    for (int c = grp * 96; c < grp * 96 + 96; ++c) {
        float v = base[(size_t)c * 4096 + tok];
        s += v; q += v * v;
    }
    __shared__ float ssum[4][64], ssq[4][64];
    __shared__ float smean[64], srstd[64];
    ssum[grp][tok] = s; ssq[grp][tok] = q;
    __syncthreads();
    if (t < 64) {
        float S = ssum[0][t] + ssum[1][t] + ssum[2][t] + ssum[3][t];
        float Q = ssq [0][t] + ssq [1][t] + ssq [2][t] + ssq [3][t];
        float m = S * (1.f / 384.f);
        float v = Q * (1.f / 384.f) - m * m;
        smean[t] = m;
        srstd[t] = rsqrtf(v + 1e-5f);
    }
    __syncthreads();

    // pass 2: normalize + permute to window order (writes coalesced along c)
    const int hh = (h - 4) & 63;
    const int cl = t & 63, tq = t >> 6;        // 64 channels x 4 tokens
    for (int tb = 0; tb < 64; tb += 4) {
        int tok2 = tb + tq;
        int ww = (tok2 - 4) & 63;
        int win = b * 64 + (hh >> 3) * 8 + (ww >> 3);
        int n = (hh & 7) * 8 + (ww & 7);
        size_t orow = ((size_t)win * 64 + n) * 384;
        float m = smean[tok2], r = srstd[tok2];
        #pragma unroll
        for (int cb = 0; cb < 384; cb += 64) {
            int c = cb + cl;
            float v = base[(size_t)c * 4096 + tok2];
            g_ln1[orow + c] = (v - m) * r * gamma[c] + beta[c];
        }
    }
}

// ---------------------------------------------------------------------------
// SGEMM: C[M,N] = A[M,K] @ W[K,N] + bias (+ optional exact GELU)
// 128x128 block tile, BK=8, 256 threads, 8x8 per thread, double-buffered smem.
// M=65536, and N,K always multiples of 128/8 -> no edge handling.
// ---------------------------------------------------------------------------
template<int SRC, int DST, int N, int K, int EPI>
__global__ void __launch_bounds__(256) sgemm_kernel(const float* __restrict__ W,
                                                    const float* __restrict__ bias) {
    __shared__ float As[2][8][128];
    __shared__ float Bs[2][8][128];
    const float* A    = gbuf<SRC>();
    float*       Cout = gbuf<DST>();

    const int bm = blockIdx.y << 7;
    const int bn = blockIdx.x << 7;
    const int t  = threadIdx.x;
    const int arow = t >> 1,  acol = (t & 1) << 2;    // A tile 128x8
    const int brow = t >> 5,  bcol = (t & 31) << 2;   // B tile 8x128
    const float* Ap = A + (size_t)(bm + arow) * K + acol;
    const float* Bp = W + (size_t)brow * N + bn + bcol;
    const int tx = (t & 15) << 3;
    const int ty = (t >> 4) << 3;

    float acc[8][8];
    #pragma unroll
    for (int i = 0; i < 8; ++i)
        #pragma unroll
        for (int j = 0; j < 8; ++j) acc[i][j] = 0.f;

    // prologue: tile 0 into buffer 0
    float4 a4 = *(const float4*)Ap;
    float4 b4 = *(const float4*)Bp;
    As[0][acol + 0][arow] = a4.x;
    As[0][acol + 1][arow] = a4.y;
    As[0][acol + 2][arow] = a4.z;
    As[0][acol + 3][arow] = a4.w;
    *(float4*)&Bs[0][brow][bcol] = b4;
    __syncthreads();

    constexpr int NIT = K / 8;
    int cur = 0;
    for (int it = 0; it < NIT; ++it) {
        if (it + 1 < NIT) {
            Ap += 8;
            Bp += (size_t)8 * N;
            a4 = *(const float4*)Ap;
            b4 = *(const float4*)Bp;
        }
        #pragma unroll
        for (int kk = 0; kk < 8; ++kk) {
            float ar[8], br[8];
            *(float4*)&ar[0] = *(const float4*)&As[cur][kk][ty];
            *(float4*)&ar[4] = *(const float4*)&As[cur][kk][ty + 4];
            *(float4*)&br[0] = *(const float4*)&Bs[cur][kk][tx];
            *(float4*)&br[4] = *(const float4*)&Bs[cur][kk][tx + 4];
            #pragma unroll
            for (int i = 0; i < 8; ++i)
                #pragma unroll
                for (int j = 0; j < 8; ++j)
                    acc[i][j] = fmaf(ar[i], br[j], acc[i][j]);
        }
        if (it + 1 < NIT) {
            int nxt = cur ^ 1;
            As[nxt][acol + 0][arow] = a4.x;
            As[nxt][acol + 1][arow] = a4.y;
            As[nxt][acol + 2][arow] = a4.z;
            As[nxt][acol + 3][arow] = a4.w;
            *(float4*)&Bs[nxt][brow][bcol] = b4;
        }
        __syncthreads();
        cur ^= 1;
    }

    // epilogue: bias (+GELU), vectorized stores
    float bv[8];
    *(float4*)&bv[0] = *(const float4*)&bias[bn + tx];
    *(float4*)&bv[4] = *(const float4*)&bias[bn + tx + 4];
    #pragma unroll
    for (int i = 0; i < 8; ++i) {
        float* Cp = Cout + (size_t)(bm + ty + i) * N + bn + tx;
        float o[8];
        #pragma unroll
        for (int j = 0; j < 8; ++j) {
            float v = acc[i][j] + bv[j];
            if (EPI == 1)
                v = 0.5f * v * (1.0f + erff(v * 0.70710678118654752f));
            o[j] = v;
        }
        *(float4*)&Cp[0] = *(float4*)&o[0];
        *(float4*)&Cp[4] = *(float4*)&o[4];
    }
}

// ---------------------------------------------------------------------------
// Kernel 3: windowed attention. One block per (win, head): 8192 blocks.
// q,k,v are (64,48). Computes softmax(q k^T * 48^-0.5) @ v entirely in
// smem/registers (no S matrix in gmem), then scatters the output row to the
// NATURAL token order (fuses window_reverse + un-shift; legal since proj is
// a row-wise linear layer).
// ---------------------------------------------------------------------------
__global__ void __launch_bounds__(256) attn_kernel() {
    __shared__ float qs[64][49];
    __shared__ float ks[64][49];
    __shared__ float vs[64][49];
    const int blk = blockIdx.x;
    const int win = blk >> 3, head = blk & 7;
    const int t = threadIdx.x;

    for (int idx = t; idx < 64 * 48; idx += 256) {
        int n = idx / 48, d = idx - n * 48;
        size_t row = ((size_t)win * 64 + n) * 1152 + head * 48 + d;
        qs[n][d] = g_qkv[row];
        ks[n][d] = g_qkv[row + 384];
        vs[n][d] = g_qkv[row + 768];
    }
    __syncthreads();

    const int i  = t >> 2;        // query row 0..63
    const int q4 = t & 3;         // quad lane: 16 key columns each

    float vals[16];
    float rmax = -1e30f;
    #pragma unroll
    for (int jj = 0; jj < 16; ++jj) {
        int j = q4 * 16 + jj;
        float s = 0.f;
        #pragma unroll
        for (int d = 0; d < 48; ++d) s = fmaf(qs[i][d], ks[j][d], s);
        s *= 0.14433756729740643f;   // 48^-0.5
        vals[jj] = s;
        rmax = fmaxf(rmax, s);
    }
    rmax = fmaxf(rmax, __shfl_xor_sync(0xffffffffu, rmax, 1));
    rmax = fmaxf(rmax, __shfl_xor_sync(0xffffffffu, rmax, 2));

    float rsum = 0.f;
    #pragma unroll
    for (int jj = 0; jj < 16; ++jj) {
        vals[jj] = expf(vals[jj] - rmax);
        rsum += vals[jj];
    }
    rsum += __shfl_xor_sync(0xffffffffu, rsum, 1);
    rsum += __shfl_xor_sync(0xffffffffu, rsum, 2);
    const float inv = 1.0f / rsum;

    // partial out over this lane's 16 keys, all 48 dims
    float o[48];
    #pragma unroll
    for (int d = 0; d < 48; ++d) o[d] = 0.f;
    #pragma unroll
    for (int jj = 0; jj < 16; ++jj) {
        float a = vals[jj] * inv;
        int m = q4 * 16 + jj;
        #pragma unroll
        for (int d = 0; d < 48; ++d) o[d] = fmaf(a, vs[m][d], o[d]);
    }
    // reduce across the quad
    #pragma unroll
    for (int d = 0; d < 48; ++d) {
        o[d] += __shfl_xor_sync(0xffffffffu, o[d], 1);
        o[d] += __shfl_xor_sync(0xffffffffu, o[d], 2);
    }

    // quad leader writes the full 48-wide head slice at the NATURAL token row
    if (q4 == 0) {
        int b   = win >> 6;
        int wh  = (win >> 3) & 7;
        int wwn = win & 7;
        int hh  = ((wh  << 3) + (i >> 3) + 4) & 63;
        int ww  = ((wwn << 3) + (i & 7)  + 4) & 63;
        size_t nat = (size_t)b * 4096 + hh * 64 + ww;
        float* op = g_att + nat * 384 + head * 48;
        #pragma unroll
        for (int d = 0; d < 48; d += 4)
            *(float4*)&op[d] = *(float4*)&o[d];
    }
}

// ---------------------------------------------------------------------------
// Kernel 5: LayerNorm2 over g_xc rows (contiguous 384 floats). Warp per token.
// ---------------------------------------------------------------------------
__global__ void __launch_bounds__(256) ln2_kernel(const float* __restrict__ gamma,
                                                  const float* __restrict__ beta) {
    const int row  = blockIdx.x * 8 + (threadIdx.x >> 5);
    const int lane = threadIdx.x & 31;
    const float* in = g_xc + (size_t)row * 384;
    float v[12];
    float s = 0.f, q = 0.f;
    #pragma unroll
    for (int k = 0; k < 12; ++k) {
        v[k] = in[lane + k * 32];
        s += v[k]; q += v[k] * v[k];
    }
    #pragma unroll
    for (int o = 16; o; o >>= 1) {
        s += __shfl_xor_sync(0xffffffffu, s, o);
        q += __shfl_xor_sync(0xffffffffu, q, o);
    }
    float m = s * (1.f / 384.f);
    float var = q * (1.f / 384.f) - m * m;
    float r = rsqrtf(var + 1e-5f);
    float* out = g_ln2 + (size_t)row * 384;
    #pragma unroll
    for (int k = 0; k < 12; ++k) {
        int c = lane + k * 32;
        out[c] = (v[k] - m) * r * gamma[c] + beta[c];
    }
}

// ---------------------------------------------------------------------------
// Kernel 8: out[b,c,h,w] = xc[tok,c] + t[tok,c]  (tiled transpose + add)
// ---------------------------------------------------------------------------
__global__ void transadd_kernel(float* __restrict__ out) {
    __shared__ float tile[32][33];
    const int b  = blockIdx.z;
    const int c0 = blockIdx.x << 5;
    const int p0 = blockIdx.y << 5;
    const int tx = threadIdx.x, ty = threadIdx.y;   // 32 x 8
    #pragma unroll
    for (int j = 0; j < 32; j += 8) {
        size_t row = (size_t)b * 4096 + p0 + ty + j;
        size_t idx = row * 384 + c0 + tx;
        tile[ty + j][tx] = g_xc[idx] + g_t[idx];
    }
    __syncthreads();
    #pragma unroll
    for (int j = 0; j < 32; j += 8) {
        int c = c0 + ty + j;
        out[((size_t)b * 384 + c) * 4096 + p0 + tx] = tile[tx][ty + j];
    }
}

// ---------------------------------------------------------------------------
extern "C" void kernel_launch(void* const* d_in, const int* in_sizes, int n_in,
                              void* d_out, int out_size) {
    const float* x    = (const float*)d_in[0];
    const float* n1g  = (const float*)d_in[1];
    const float* n1b  = (const float*)d_in[2];
    const float* qkvw = (const float*)d_in[3];
    const float* qkvb = (const float*)d_in[4];
    const float* pw   = (const float*)d_in[5];
    const float* pb   = (const float*)d_in[6];
    const float* n2g  = (const float*)d_in[7];
    const float* n2b  = (const float*)d_in[8];
    const float* w1   = (const float*)d_in[9];
    const float* b1   = (const float*)d_in[10];
    const float* w2   = (const float*)d_in[11];
    const float* b2   = (const float*)d_in[12];
    float* out = (float*)d_out;

    // 1) shift + window partition + LN1  -> g_ln1 (window-ordered)
    ln1_kernel<<<1024, 256>>>(x, n1g, n1b);

    // 2) QKV GEMM: (65536x384) @ (384x1152) -> g_qkv
    sgemm_kernel<0, 1, 1152, 384, 0><<<dim3(9, 512), 256>>>(qkvw, qkvb);

    // 3) window attention -> g_att (natural token order)
    attn_kernel<<<8192, 256>>>();

    // 4) proj GEMM: (65536x384) @ (384x384) -> g_xc
    sgemm_kernel<2, 3, 384, 384, 0><<<dim3(3, 512), 256>>>(pw, pb);

    // 5) LN2 -> g_ln2
    ln2_kernel<<<8192, 256>>>(n2g, n2b);

    // 6) MLP1 GEMM + GELU: (65536x384) @ (384x1536) -> g_hid
    sgemm_kernel<4, 5, 1536, 384, 1><<<dim3(12, 512), 256>>>(w1, b1);

    // 7) MLP2 GEMM: (65536x1536) @ (1536x384) -> g_t
    sgemm_kernel<5, 6, 384, 1536, 0><<<dim3(3, 512), 256>>>(w2, b2);

    // 8) out = xc + t, transposed to (B,C,H,W)
    transadd_kernel<<<dim3(12, 128, 16), dim3(32, 8)>>>(out);
}

// round 5
// speedup vs baseline: 1.0004x; 1.0004x over previous
#include <cuda_runtime.h>
#include <math.h>

// ---------------------------------------------------------------------------
// SwinTransformerBlock  B=16, C=384, H=W=64, WS=8, SHIFT=4, HEADS=8, hd=48
// 65536 tokens. All fp32.
// ---------------------------------------------------------------------------

static constexpr int TOKS = 65536;   // B*H*W

// Scratch (zero-init .bss style device globals; no runtime allocation)
__device__ float g_ln1[25165824];    // 65536*384   LN1 output, window-ordered
__device__ float g_qkv[75497472];    // 65536*1152  QKV output, window-ordered
__device__ float g_att[25165824];    // 65536*384   attn output, NATURAL order
__device__ float g_xc [25165824];    // 65536*384   proj output (xc), natural
__device__ float g_ln2[25165824];    // 65536*384   LN2 output
__device__ float g_hid[100663296];   // 65536*1536  MLP hidden
__device__ float g_t  [25165824];    // 65536*384   MLP output (t)

template<int ID> __device__ __forceinline__ float* gbuf();
template<> __device__ __forceinline__ float* gbuf<0>() { return g_ln1; }
template<> __device__ __forceinline__ float* gbuf<1>() { return g_qkv; }
template<> __device__ __forceinline__ float* gbuf<2>() { return g_att; }
template<> __device__ __forceinline__ float* gbuf<3>() { return g_xc;  }
template<> __device__ __forceinline__ float* gbuf<4>() { return g_ln2; }
template<> __device__ __forceinline__ float* gbuf<5>() { return g_hid; }
template<> __device__ __forceinline__ float* gbuf<6>() { return g_t;   }

// ---------------------------------------------------------------------------
// Kernel 1: shift + window partition + LayerNorm1.
// One block per (b, h) image row (1024 blocks). Input x is (B,C,H,W).
// Output row index = window-ordered token id: win*64 + n  where the token's
// shifted coords are hh' = (h-4)&63, ww' = (w-4)&63.
// ---------------------------------------------------------------------------
__global__ void __launch_bounds__(256) ln1_kernel(const float* __restrict__ x,
                                                  const float* __restrict__ gamma,
                                                  const float* __restrict__ beta) {
    const int bh = blockIdx.x;
    const int b = bh >> 6, h = bh & 63;
    const int t = threadIdx.x;                 // 256
    const int tok = t & 63, grp = t >> 6;      // 64 tokens x 4 channel groups
    const float* base = x + (size_t)b * 384 * 4096 + h * 64;

    // pass 1: per-token sum / sumsq (coalesced: fixed c, 64 consecutive w)
    float s = 0.f, q = 0.f;
    for (int c = grp * 96; c < grp * 96 + 96; ++c) {
        float v = base[(size_t)c * 4096 + tok];
        s += v; q += v * v;
    }
    __shared__ float ssum[4][64], ssq[4][64];
    __shared__ float smean[64], srstd[64];
    ssum[grp][tok] = s; ssq[grp][tok] = q;
    __syncthreads();
    if (t < 64) {
        float S = ssum[0][t] + ssum[1][t] + ssum[2][t] + ssum[3][t];
        float Q = ssq [0][t] + ssq [1][t] + ssq [2][t] + ssq [3][t];
        float m = S * (1.f / 384.f);
        float v = Q * (1.f / 384.f) - m * m;
        smean[t] = m;
        srstd[t] = rsqrtf(v + 1e-5f);
    }
    __syncthreads();

    // pass 2: normalize + permute to window order (writes coalesced along c)
    const int hh = (h - 4) & 63;
    const int cl = t & 63, tq = t >> 6;        // 64 channels x 4 tokens
    for (int tb = 0; tb < 64; tb += 4) {
        int tok2 = tb + tq;
        int ww = (tok2 - 4) & 63;
        int win = b * 64 + (hh >> 3) * 8 + (ww >> 3);
        int n = (hh & 7) * 8 + (ww & 7);
        size_t orow = ((size_t)win * 64 + n) * 384;
        float m = smean[tok2], r = srstd[tok2];
        #pragma unroll
        for (int cb = 0; cb < 384; cb += 64) {
            int c = cb + cl;
            float v = base[(size_t)c * 4096 + tok2];
            g_ln1[orow + c] = (v - m) * r * gamma[c] + beta[c];
        }
    }
}

// ---------------------------------------------------------------------------
// SGEMM: C[M,N] = A[M,K] @ W[K,N] + bias (+ optional exact GELU)
// 128x128 block tile, BK=8, 256 threads, 8x8 per thread, double-buffered smem.
// M=65536, and N,K always multiples of 128/8 -> no edge handling.
// ---------------------------------------------------------------------------
template<int SRC, int DST, int N, int K, int EPI>
__global__ void __launch_bounds__(256) sgemm_kernel(const float* __restrict__ W,
                                                    const float* __restrict__ bias) {
    __shared__ float As[2][8][128];
    __shared__ float Bs[2][8][128];
    const float* A    = gbuf<SRC>();
    float*       Cout = gbuf<DST>();

    const int bm = blockIdx.y << 7;
    const int bn = blockIdx.x << 7;
    const int t  = threadIdx.x;
    const int arow = t >> 1,  acol = (t & 1) << 2;    // A tile 128x8
    const int brow = t >> 5,  bcol = (t & 31) << 2;   // B tile 8x128
    const float* Ap = A + (size_t)(bm + arow) * K + acol;
    const float* Bp = W + (size_t)brow * N + bn + bcol;
    const int tx = (t & 15) << 3;
    const int ty = (t >> 4) << 3;

    float acc[8][8];
    #pragma unroll
    for (int i = 0; i < 8; ++i)
        #pragma unroll
        for (int j = 0; j < 8; ++j) acc[i][j] = 0.f;

    // prologue: tile 0 into buffer 0
    float4 a4 = *(const float4*)Ap;
    float4 b4 = *(const float4*)Bp;
    As[0][acol + 0][arow] = a4.x;
    As[0][acol + 1][arow] = a4.y;
    As[0][acol + 2][arow] = a4.z;
    As[0][acol + 3][arow] = a4.w;
    *(float4*)&Bs[0][brow][bcol] = b4;
    __syncthreads();

    constexpr int NIT = K / 8;
    int cur = 0;
    for (int it = 0; it < NIT; ++it) {
        if (it + 1 < NIT) {
            Ap += 8;
            Bp += (size_t)8 * N;
            a4 = *(const float4*)Ap;
            b4 = *(const float4*)Bp;
        }
        #pragma unroll
        for (int kk = 0; kk < 8; ++kk) {
            float ar[8], br[8];
            *(float4*)&ar[0] = *(const float4*)&As[cur][kk][ty];
            *(float4*)&ar[4] = *(const float4*)&As[cur][kk][ty + 4];
            *(float4*)&br[0] = *(const float4*)&Bs[cur][kk][tx];
            *(float4*)&br[4] = *(const float4*)&Bs[cur][kk][tx + 4];
            #pragma unroll
            for (int i = 0; i < 8; ++i)
                #pragma unroll
                for (int j = 0; j < 8; ++j)
                    acc[i][j] = fmaf(ar[i], br[j], acc[i][j]);
        }
        if (it + 1 < NIT) {
            int nxt = cur ^ 1;
            As[nxt][acol + 0][arow] = a4.x;
            As[nxt][acol + 1][arow] = a4.y;
            As[nxt][acol + 2][arow] = a4.z;
            As[nxt][acol + 3][arow] = a4.w;
            *(float4*)&Bs[nxt][brow][bcol] = b4;
        }
        __syncthreads();
        cur ^= 1;
    }

    // epilogue: bias (+GELU), vectorized stores
    float bv[8];
    *(float4*)&bv[0] = *(const float4*)&bias[bn + tx];
    *(float4*)&bv[4] = *(const float4*)&bias[bn + tx + 4];
    #pragma unroll
    for (int i = 0; i < 8; ++i) {
        float* Cp = Cout + (size_t)(bm + ty + i) * N + bn + tx;
        float o[8];
        #pragma unroll
        for (int j = 0; j < 8; ++j) {
            float v = acc[i][j] + bv[j];
            if (EPI == 1)
                v = 0.5f * v * (1.0f + erff(v * 0.70710678118654752f));
            o[j] = v;
        }
        *(float4*)&Cp[0] = *(float4*)&o[0];
        *(float4*)&Cp[4] = *(float4*)&o[4];
    }
}

// ---------------------------------------------------------------------------
// Kernel 3: windowed attention. One block per (win, head): 8192 blocks.
// q,k,v are (64,48). Computes softmax(q k^T * 48^-0.5) @ v entirely in
// smem/registers (no S matrix in gmem), then scatters the output row to the
// NATURAL token order (fuses window_reverse + un-shift; legal since proj is
// a row-wise linear layer).
// ---------------------------------------------------------------------------
__global__ void __launch_bounds__(256) attn_kernel() {
    __shared__ float qs[64][49];
    __shared__ float ks[64][49];
    __shared__ float vs[64][49];
    const int blk = blockIdx.x;
    const int win = blk >> 3, head = blk & 7;
    const int t = threadIdx.x;

    for (int idx = t; idx < 64 * 48; idx += 256) {
        int n = idx / 48, d = idx - n * 48;
        size_t row = ((size_t)win * 64 + n) * 1152 + head * 48 + d;
        qs[n][d] = g_qkv[row];
        ks[n][d] = g_qkv[row + 384];
        vs[n][d] = g_qkv[row + 768];
    }
    __syncthreads();

    const int i  = t >> 2;        // query row 0..63
    const int q4 = t & 3;         // quad lane: 16 key columns each

    float vals[16];
    float rmax = -1e30f;
    #pragma unroll
    for (int jj = 0; jj < 16; ++jj) {
        int j = q4 * 16 + jj;
        float s = 0.f;
        #pragma unroll
        for (int d = 0; d < 48; ++d) s = fmaf(qs[i][d], ks[j][d], s);
        s *= 0.14433756729740643f;   // 48^-0.5
        vals[jj] = s;
        rmax = fmaxf(rmax, s);
    }
    rmax = fmaxf(rmax, __shfl_xor_sync(0xffffffffu, rmax, 1));
    rmax = fmaxf(rmax, __shfl_xor_sync(0xffffffffu, rmax, 2));

    float rsum = 0.f;
    #pragma unroll
    for (int jj = 0; jj < 16; ++jj) {
        vals[jj] = expf(vals[jj] - rmax);
        rsum += vals[jj];
    }
    rsum += __shfl_xor_sync(0xffffffffu, rsum, 1);
    rsum += __shfl_xor_sync(0xffffffffu, rsum, 2);
    const float inv = 1.0f / rsum;

    // partial out over this lane's 16 keys, all 48 dims
    float o[48];
    #pragma unroll
    for (int d = 0; d < 48; ++d) o[d] = 0.f;
    #pragma unroll
    for (int jj = 0; jj < 16; ++jj) {
        float a = vals[jj] * inv;
        int m = q4 * 16 + jj;
        #pragma unroll
        for (int d = 0; d < 48; ++d) o[d] = fmaf(a, vs[m][d], o[d]);
    }
    // reduce across the quad
    #pragma unroll
    for (int d = 0; d < 48; ++d) {
        o[d] += __shfl_xor_sync(0xffffffffu, o[d], 1);
        o[d] += __shfl_xor_sync(0xffffffffu, o[d], 2);
    }

    // quad leader writes the full 48-wide head slice at the NATURAL token row
    if (q4 == 0) {
        int b   = win >> 6;
        int wh  = (win >> 3) & 7;
        int wwn = win & 7;
        int hh  = ((wh  << 3) + (i >> 3) + 4) & 63;
        int ww  = ((wwn << 3) + (i & 7)  + 4) & 63;
        size_t nat = (size_t)b * 4096 + hh * 64 + ww;
        float* op = g_att + nat * 384 + head * 48;
        #pragma unroll
        for (int d = 0; d < 48; d += 4)
            *(float4*)&op[d] = *(float4*)&o[d];
    }
}

// ---------------------------------------------------------------------------
// Kernel 5: LayerNorm2 over g_xc rows (contiguous 384 floats). Warp per token.
// ---------------------------------------------------------------------------
__global__ void __launch_bounds__(256) ln2_kernel(const float* __restrict__ gamma,
                                                  const float* __restrict__ beta) {
    const int row  = blockIdx.x * 8 + (threadIdx.x >> 5);
    const int lane = threadIdx.x & 31;
    const float* in = g_xc + (size_t)row * 384;
    float v[12];
    float s = 0.f, q = 0.f;
    #pragma unroll
    for (int k = 0; k < 12; ++k) {
        v[k] = in[lane + k * 32];
        s += v[k]; q += v[k] * v[k];
    }
    #pragma unroll
    for (int o = 16; o; o >>= 1) {
        s += __shfl_xor_sync(0xffffffffu, s, o);
        q += __shfl_xor_sync(0xffffffffu, q, o);
    }
    float m = s * (1.f / 384.f);
    float var = q * (1.f / 384.f) - m * m;
    float r = rsqrtf(var + 1e-5f);
    float* out = g_ln2 + (size_t)row * 384;
    #pragma unroll
    for (int k = 0; k < 12; ++k) {
        int c = lane + k * 32;
        out[c] = (v[k] - m) * r * gamma[c] + beta[c];
    }
}

// ---------------------------------------------------------------------------
// Kernel 8: out[b,c,h,w] = xc[tok,c] + t[tok,c]  (tiled transpose + add)
// ---------------------------------------------------------------------------
__global__ void transadd_kernel(float* __restrict__ out) {
    __shared__ float tile[32][33];
    const int b  = blockIdx.z;
    const int c0 = blockIdx.x << 5;
    const int p0 = blockIdx.y << 5;
    const int tx = threadIdx.x, ty = threadIdx.y;   // 32 x 8
    #pragma unroll
    for (int j = 0; j < 32; j += 8) {
        size_t row = (size_t)b * 4096 + p0 + ty + j;
        size_t idx = row * 384 + c0 + tx;
        tile[ty + j][tx] = g_xc[idx] + g_t[idx];
    }
    __syncthreads();
    #pragma unroll
    for (int j = 0; j < 32; j += 8) {
        int c = c0 + ty + j;
        out[((size_t)b * 384 + c) * 4096 + p0 + tx] = tile[tx][ty + j];
    }
}

// ---------------------------------------------------------------------------
extern "C" void kernel_launch(void* const* d_in, const int* in_sizes, int n_in,
                              void* d_out, int out_size) {
    const float* x    = (const float*)d_in[0];
    const float* n1g  = (const float*)d_in[1];
    const float* n1b  = (const float*)d_in[2];
    const float* qkvw = (const float*)d_in[3];
    const float* qkvb = (const float*)d_in[4];
    const float* pw   = (const float*)d_in[5];
    const float* pb   = (const float*)d_in[6];
    const float* n2g  = (const float*)d_in[7];
    const float* n2b  = (const float*)d_in[8];
    const float* w1   = (const float*)d_in[9];
    const float* b1   = (const float*)d_in[10];
    const float* w2   = (const float*)d_in[11];
    const float* b2   = (const float*)d_in[12];
    float* out = (float*)d_out;

    // 1) shift + window partition + LN1  -> g_ln1 (window-ordered)
    ln1_kernel<<<1024, 256>>>(x, n1g, n1b);

    // 2) QKV GEMM: (65536x384) @ (384x1152) -> g_qkv
    sgemm_kernel<0, 1, 1152, 384, 0><<<dim3(9, 512), 256>>>(qkvw, qkvb);

    // 3) window attention -> g_att (natural token order)
    attn_kernel<<<8192, 256>>>();

    // 4) proj GEMM: (65536x384) @ (384x384) -> g_xc
    sgemm_kernel<2, 3, 384, 384, 0><<<dim3(3, 512), 256>>>(pw, pb);

    // 5) LN2 -> g_ln2
    ln2_kernel<<<8192, 256>>>(n2g, n2b);

    // 6) MLP1 GEMM + GELU: (65536x384) @ (384x1536) -> g_hid
    sgemm_kernel<4, 5, 1536, 384, 1><<<dim3(12, 512), 256>>>(w1, b1);

    // 7) MLP2 GEMM: (65536x1536) @ (1536x384) -> g_t
    sgemm_kernel<5, 6, 384, 1536, 0><<<dim3(3, 512), 256>>>(w2, b2);

    // 8) out = xc + t, transposed to (B,C,H,W)
    transadd_kernel<<<dim3(12, 128, 16), dim3(32, 8)>>>(out);
}

// round 6
// speedup vs baseline: 2.1400x; 2.1391x over previous
#include <cuda_runtime.h>
#include <math.h>

// ---------------------------------------------------------------------------
// SwinTransformerBlock  B=16, C=384, H=W=64, WS=8, SHIFT=4, HEADS=8, hd=48
// 65536 tokens. GEMMs on tensor cores (tf32 mma.sync), rest fp32.
// ---------------------------------------------------------------------------

// Scratch (device globals; no runtime allocation)
__device__ float g_ln1[25165824];    // 65536*384   LN1 output, window-ordered
__device__ float g_qkv[75497472];    // 65536*1152  QKV output, window-ordered
__device__ float g_att[25165824];    // 65536*384   attn output, NATURAL order
__device__ float g_xc [25165824];    // 65536*384   proj output (xc), natural
__device__ float g_ln2[25165824];    // 65536*384   LN2 output
__device__ float g_hid[100663296];   // 65536*1536  MLP hidden
__device__ float g_t  [25165824];    // 65536*384   MLP output (t)

template<int ID> __device__ __forceinline__ float* gbuf();
template<> __device__ __forceinline__ float* gbuf<0>() { return g_ln1; }
template<> __device__ __forceinline__ float* gbuf<1>() { return g_qkv; }
template<> __device__ __forceinline__ float* gbuf<2>() { return g_att; }
template<> __device__ __forceinline__ float* gbuf<3>() { return g_xc;  }
template<> __device__ __forceinline__ float* gbuf<4>() { return g_ln2; }
template<> __device__ __forceinline__ float* gbuf<5>() { return g_hid; }
template<> __device__ __forceinline__ float* gbuf<6>() { return g_t;   }

__device__ __forceinline__ unsigned f2tf(float f) {
    unsigned u;
    asm("cvt.rna.tf32.f32 %0, %1;" : "=r"(u) : "f"(f));
    return u;
}

__device__ __forceinline__ void mma_tf32(float c[4], const unsigned a[4], const unsigned b[2]) {
    asm volatile(
        "mma.sync.aligned.m16n8k8.row.col.f32.tf32.tf32.f32 "
        "{%0,%1,%2,%3}, {%4,%5,%6,%7}, {%8,%9}, {%0,%1,%2,%3};"
        : "+f"(c[0]), "+f"(c[1]), "+f"(c[2]), "+f"(c[3])
        : "r"(a[0]), "r"(a[1]), "r"(a[2]), "r"(a[3]), "r"(b[0]), "r"(b[1]));
}

// ---------------------------------------------------------------------------
// Kernel 1: shift + window partition + LayerNorm1 (unchanged)
// ---------------------------------------------------------------------------
__global__ void __launch_bounds__(256) ln1_kernel(const float* __restrict__ x,
                                                  const float* __restrict__ gamma,
                                                  const float* __restrict__ beta) {
    const int bh = blockIdx.x;
    const int b = bh >> 6, h = bh & 63;
    const int t = threadIdx.x;
    const int tok = t & 63, grp = t >> 6;
    const float* base = x + (size_t)b * 384 * 4096 + h * 64;

    float s = 0.f, q = 0.f;
    for (int c = grp * 96; c < grp * 96 + 96; ++c) {
        float v = base[(size_t)c * 4096 + tok];
        s += v; q += v * v;
    }
    __shared__ float ssum[4][64], ssq[4][64];
    __shared__ float smean[64], srstd[64];
    ssum[grp][tok] = s; ssq[grp][tok] = q;
    __syncthreads();
    if (t < 64) {
        float S = ssum[0][t] + ssum[1][t] + ssum[2][t] + ssum[3][t];
        float Q = ssq [0][t] + ssq [1][t] + ssq [2][t] + ssq [3][t];
        float m = S * (1.f / 384.f);
        float v = Q * (1.f / 384.f) - m * m;
        smean[t] = m;
        srstd[t] = rsqrtf(v + 1e-5f);
    }
    __syncthreads();

    const int hh = (h - 4) & 63;
    const int cl = t & 63, tq = t >> 6;
    for (int tb = 0; tb < 64; tb += 4) {
        int tok2 = tb + tq;
        int ww = (tok2 - 4) & 63;
        int win = b * 64 + (hh >> 3) * 8 + (ww >> 3);
        int n = (hh & 7) * 8 + (ww & 7);
        size_t orow = ((size_t)win * 64 + n) * 384;
        float m = smean[tok2], r = srstd[tok2];
        #pragma unroll
        for (int cb = 0; cb < 384; cb += 64) {
            int c = cb + cl;
            float v = base[(size_t)c * 4096 + tok2];
            g_ln1[orow + c] = (v - m) * r * gamma[c] + beta[c];
        }
    }
}

// ---------------------------------------------------------------------------
// TF32 tensor-core GEMM: C[M,N] = A[M,K] @ W[K,N] + bias (+ optional GELU)
// 128x128 block tile, BK=16, 256 threads = 8 warps (4m x 2n), warp 32x64.
// mma.sync.m16n8k8 tf32. Double-buffered smem. A: [m][k] stride 20 (frag-load
// conflict-free); B: [k][n] stride 136 (conflict-free).
// ---------------------------------------------------------------------------
template<int SRC, int DST, int N, int K, int EPI>
__global__ void __launch_bounds__(256) tgemm_kernel(const float* __restrict__ W,
                                                    const float* __restrict__ bias) {
    __shared__ float As[2][128 * 20];   // [m][k], stride 20
    __shared__ float Bs[2][16 * 136];   // [k][n], stride 136
    const float* A    = gbuf<SRC>();
    float*       Cout = gbuf<DST>();

    const int bm = blockIdx.y << 7;
    const int bn = blockIdx.x << 7;
    const int t    = threadIdx.x;
    const int warp = t >> 5, lane = t & 31;
    const int wm = warp >> 1;          // 0..3 -> m offset wm*32
    const int wn = warp & 1;           // 0..1 -> n offset wn*64
    const int gid = lane >> 2, tig = lane & 3;

    // global A: 128 rows x 16 cols; thread loads float4 at (rowA, colv) and (rowA+64, colv)
    const int rowA = t >> 2;           // 0..63
    const int colv = (t & 3) << 2;     // 0,4,8,12
    const float* Ap = A + (size_t)(bm + rowA) * K + colv;
    // global B: 16 rows x 128 cols; thread loads float4 at (rowB, colB) and (rowB+8, colB)
    const int rowB = t >> 5;           // 0..7
    const int colB = (t & 31) << 2;
    const float* Bp = W + (size_t)rowB * N + bn + colB;

    float acc[2][8][4];
    #pragma unroll
    for (int mt = 0; mt < 2; ++mt)
        #pragma unroll
        for (int nt = 0; nt < 8; ++nt)
            #pragma unroll
            for (int r = 0; r < 4; ++r) acc[mt][nt][r] = 0.f;

    float4 a0 = *(const float4*)Ap;
    float4 a1 = *(const float4*)(Ap + (size_t)64 * K);
    float4 b0 = *(const float4*)Bp;
    float4 b1 = *(const float4*)(Bp + (size_t)8 * N);

    auto stage = [&](int buf, float4 A0, float4 A1, float4 B0, float4 B1) {
        unsigned* ap0 = (unsigned*)&As[buf][rowA * 20 + colv];
        unsigned* ap1 = (unsigned*)&As[buf][(rowA + 64) * 20 + colv];
        *(uint4*)ap0 = make_uint4(f2tf(A0.x), f2tf(A0.y), f2tf(A0.z), f2tf(A0.w));
        *(uint4*)ap1 = make_uint4(f2tf(A1.x), f2tf(A1.y), f2tf(A1.z), f2tf(A1.w));
        unsigned* bp0 = (unsigned*)&Bs[buf][rowB * 136 + colB];
        unsigned* bp1 = (unsigned*)&Bs[buf][(rowB + 8) * 136 + colB];
        *(uint4*)bp0 = make_uint4(f2tf(B0.x), f2tf(B0.y), f2tf(B0.z), f2tf(B0.w));
        *(uint4*)bp1 = make_uint4(f2tf(B1.x), f2tf(B1.y), f2tf(B1.z), f2tf(B1.w));
    };

    stage(0, a0, a1, b0, b1);
    __syncthreads();

    constexpr int NIT = K / 16;
    int cur = 0;
    for (int it = 0; it < NIT; ++it) {
        if (it + 1 < NIT) {
            Ap += 16;
            Bp += (size_t)16 * N;
            a0 = *(const float4*)Ap;
            a1 = *(const float4*)(Ap + (size_t)64 * K);
            b0 = *(const float4*)Bp;
            b1 = *(const float4*)(Bp + (size_t)8 * N);
        }
        const unsigned* Asp = (const unsigned*)As[cur];
        const unsigned* Bsp = (const unsigned*)Bs[cur];
        #pragma unroll
        for (int ks = 0; ks < 16; ks += 8) {
            unsigned af[2][4], bf[8][2];
            #pragma unroll
            for (int mt = 0; mt < 2; ++mt) {
                int m0 = wm * 32 + mt * 16 + gid;
                af[mt][0] = Asp[m0 * 20 + ks + tig];
                af[mt][1] = Asp[(m0 + 8) * 20 + ks + tig];
                af[mt][2] = Asp[m0 * 20 + ks + tig + 4];
                af[mt][3] = Asp[(m0 + 8) * 20 + ks + tig + 4];
            }
            #pragma unroll
            for (int nt = 0; nt < 8; ++nt) {
                int n0 = wn * 64 + nt * 8 + gid;
                bf[nt][0] = Bsp[(ks + tig) * 136 + n0];
                bf[nt][1] = Bsp[(ks + tig + 4) * 136 + n0];
            }
            #pragma unroll
            for (int mt = 0; mt < 2; ++mt)
                #pragma unroll
                for (int nt = 0; nt < 8; ++nt)
                    mma_tf32(acc[mt][nt], af[mt], bf[nt]);
        }
        if (it + 1 < NIT) stage(cur ^ 1, a0, a1, b0, b1);
        __syncthreads();
        cur ^= 1;
    }

    // epilogue
    #pragma unroll
    for (int mt = 0; mt < 2; ++mt) {
        int mrow = bm + wm * 32 + mt * 16 + gid;
        #pragma unroll
        for (int nt = 0; nt < 8; ++nt) {
            int n = bn + wn * 64 + nt * 8 + tig * 2;
            float bvx = bias[n], bvy = bias[n + 1];
            float v0 = acc[mt][nt][0] + bvx;
            float v1 = acc[mt][nt][1] + bvy;
            float v2 = acc[mt][nt][2] + bvx;
            float v3 = acc[mt][nt][3] + bvy;
            if (EPI == 1) {
                v0 = 0.5f * v0 * (1.0f + erff(v0 * 0.70710678118654752f));
                v1 = 0.5f * v1 * (1.0f + erff(v1 * 0.70710678118654752f));
                v2 = 0.5f * v2 * (1.0f + erff(v2 * 0.70710678118654752f));
                v3 = 0.5f * v3 * (1.0f + erff(v3 * 0.70710678118654752f));
            }
            *(float2*)&Cout[(size_t)mrow * N + n]       = make_float2(v0, v1);
            *(float2*)&Cout[(size_t)(mrow + 8) * N + n] = make_float2(v2, v3);
        }
    }
}

// ---------------------------------------------------------------------------
// Kernel 3: windowed attention (unchanged). One block per (win, head).
// ---------------------------------------------------------------------------
__global__ void __launch_bounds__(256) attn_kernel() {
    __shared__ float qs[64][49];
    __shared__ float ks[64][49];
    __shared__ float vs[64][49];
    const int blk = blockIdx.x;
    const int win = blk >> 3, head = blk & 7;
    const int t = threadIdx.x;

    for (int idx = t; idx < 64 * 48; idx += 256) {
        int n = idx / 48, d = idx - n * 48;
        size_t row = ((size_t)win * 64 + n) * 1152 + head * 48 + d;
        qs[n][d] = g_qkv[row];
        ks[n][d] = g_qkv[row + 384];
        vs[n][d] = g_qkv[row + 768];
    }
    __syncthreads();

    const int i  = t >> 2;
    const int q4 = t & 3;

    float vals[16];
    float rmax = -1e30f;
    #pragma unroll
    for (int jj = 0; jj < 16; ++jj) {
        int j = q4 * 16 + jj;
        float s = 0.f;
        #pragma unroll
        for (int d = 0; d < 48; ++d) s = fmaf(qs[i][d], ks[j][d], s);
        s *= 0.14433756729740643f;
        vals[jj] = s;
        rmax = fmaxf(rmax, s);
    }
    rmax = fmaxf(rmax, __shfl_xor_sync(0xffffffffu, rmax, 1));
    rmax = fmaxf(rmax, __shfl_xor_sync(0xffffffffu, rmax, 2));

    float rsum = 0.f;
    #pragma unroll
    for (int jj = 0; jj < 16; ++jj) {
        vals[jj] = expf(vals[jj] - rmax);
        rsum += vals[jj];
    }
    rsum += __shfl_xor_sync(0xffffffffu, rsum, 1);
    rsum += __shfl_xor_sync(0xffffffffu, rsum, 2);
    const float inv = 1.0f / rsum;

    float o[48];
    #pragma unroll
    for (int d = 0; d < 48; ++d) o[d] = 0.f;
    #pragma unroll
    for (int jj = 0; jj < 16; ++jj) {
        float a = vals[jj] * inv;
        int m = q4 * 16 + jj;
        #pragma unroll
        for (int d = 0; d < 48; ++d) o[d] = fmaf(a, vs[m][d], o[d]);
    }
    #pragma unroll
    for (int d = 0; d < 48; ++d) {
        o[d] += __shfl_xor_sync(0xffffffffu, o[d], 1);
        o[d] += __shfl_xor_sync(0xffffffffu, o[d], 2);
    }

    if (q4 == 0) {
        int b   = win >> 6;
        int wh  = (win >> 3) & 7;
        int wwn = win & 7;
        int hh  = ((wh  << 3) + (i >> 3) + 4) & 63;
        int ww  = ((wwn << 3) + (i & 7)  + 4) & 63;
        size_t nat = (size_t)b * 4096 + hh * 64 + ww;
        float* op = g_att + nat * 384 + head * 48;
        #pragma unroll
        for (int d = 0; d < 48; d += 4)
            *(float4*)&op[d] = *(float4*)&o[d];
    }
}

// ---------------------------------------------------------------------------
// Kernel 5: LayerNorm2 (unchanged)
// ---------------------------------------------------------------------------
__global__ void __launch_bounds__(256) ln2_kernel(const float* __restrict__ gamma,
                                                  const float* __restrict__ beta) {
    const int row  = blockIdx.x * 8 + (threadIdx.x >> 5);
    const int lane = threadIdx.x & 31;
    const float* in = g_xc + (size_t)row * 384;
    float v[12];
    float s = 0.f, q = 0.f;
    #pragma unroll
    for (int k = 0; k < 12; ++k) {
        v[k] = in[lane + k * 32];
        s += v[k]; q += v[k] * v[k];
    }
    #pragma unroll
    for (int o = 16; o; o >>= 1) {
        s += __shfl_xor_sync(0xffffffffu, s, o);
        q += __shfl_xor_sync(0xffffffffu, q, o);
    }
    float m = s * (1.f / 384.f);
    float var = q * (1.f / 384.f) - m * m;
    float r = rsqrtf(var + 1e-5f);
    float* out = g_ln2 + (size_t)row * 384;
    #pragma unroll
    for (int k = 0; k < 12; ++k) {
        int c = lane + k * 32;
        out[c] = (v[k] - m) * r * gamma[c] + beta[c];
    }
}

// ---------------------------------------------------------------------------
// Kernel 8: out[b,c,h,w] = xc[tok,c] + t[tok,c]  (tiled transpose + add)
// ---------------------------------------------------------------------------
__global__ void transadd_kernel(float* __restrict__ out) {
    __shared__ float tile[32][33];
    const int b  = blockIdx.z;
    const int c0 = blockIdx.x << 5;
    const int p0 = blockIdx.y << 5;
    const int tx = threadIdx.x, ty = threadIdx.y;
    #pragma unroll
    for (int j = 0; j < 32; j += 8) {
        size_t row = (size_t)b * 4096 + p0 + ty + j;
        size_t idx = row * 384 + c0 + tx;
        tile[ty + j][tx] = g_xc[idx] + g_t[idx];
    }
    __syncthreads();
    #pragma unroll
    for (int j = 0; j < 32; j += 8) {
        int c = c0 + ty + j;
        out[((size_t)b * 384 + c) * 4096 + p0 + tx] = tile[tx][ty + j];
    }
}

// ---------------------------------------------------------------------------
extern "C" void kernel_launch(void* const* d_in, const int* in_sizes, int n_in,
                              void* d_out, int out_size) {
    const float* x    = (const float*)d_in[0];
    const float* n1g  = (const float*)d_in[1];
    const float* n1b  = (const float*)d_in[2];
    const float* qkvw = (const float*)d_in[3];
    const float* qkvb = (const float*)d_in[4];
    const float* pw   = (const float*)d_in[5];
    const float* pb   = (const float*)d_in[6];
    const float* n2g  = (const float*)d_in[7];
    const float* n2b  = (const float*)d_in[8];
    const float* w1   = (const float*)d_in[9];
    const float* b1   = (const float*)d_in[10];
    const float* w2   = (const float*)d_in[11];
    const float* b2   = (const float*)d_in[12];
    float* out = (float*)d_out;

    // 1) shift + window partition + LN1  -> g_ln1 (window-ordered)
    ln1_kernel<<<1024, 256>>>(x, n1g, n1b);

    // 2) QKV GEMM: (65536x384) @ (384x1152) -> g_qkv
    tgemm_kernel<0, 1, 1152, 384, 0><<<dim3(9, 512), 256>>>(qkvw, qkvb);

    // 3) window attention -> g_att (natural token order)
    attn_kernel<<<8192, 256>>>();

    // 4) proj GEMM: (65536x384) @ (384x384) -> g_xc
    tgemm_kernel<2, 3, 384, 384, 0><<<dim3(3, 512), 256>>>(pw, pb);

    // 5) LN2 -> g_ln2
    ln2_kernel<<<8192, 256>>>(n2g, n2b);

    // 6) MLP1 GEMM + GELU: (65536x384) @ (384x1536) -> g_hid
    tgemm_kernel<4, 5, 1536, 384, 1><<<dim3(12, 512), 256>>>(w1, b1);

    // 7) MLP2 GEMM: (65536x1536) @ (1536x384) -> g_t
    tgemm_kernel<5, 6, 384, 1536, 0><<<dim3(3, 512), 256>>>(w2, b2);

    // 8) out = xc + t, transposed to (B,C,H,W)
    transadd_kernel<<<dim3(12, 128, 16), dim3(32, 8)>>>(out);
}